// round 3
// baseline (speedup 1.0000x reference)
#include <cuda_runtime.h>

#define B_  2
#define H_  12
#define S_  2048
#define D_  64
#define BH_ (B_ * H_)
#define SCALE_ 0.125f   // 1/sqrt(64)

// Per-row sums of unnormalized exp(logit). 24*2048 floats.
__device__ float g_rowsum[BH_ * S_];

// ---------------------------------------------------------------------------
// Kernel 0: zero the rowsum accumulator.
// ---------------------------------------------------------------------------
__global__ void zero_rowsum_kernel()
{
    g_rowsum[blockIdx.x * 256 + threadIdx.x] = 0.0f;
}

// ---------------------------------------------------------------------------
// Kernel 1: QK^T + mask + exp (unnormalized), rowsum accumulation.
// C-tile 128x128, 256 threads, 8x8 per-thread register tile.
// Double-buffered d-chunks of 16. Writes E = exp(masked logit) to attn region.
// ---------------------------------------------------------------------------
__global__ __launch_bounds__(256, 2)
void qk_exp_kernel(const float* __restrict__ q, const float* __restrict__ k,
                   const int* __restrict__ mask, float* __restrict__ attn)
{
    __shared__ float sQ[2][16][132];
    __shared__ float sK[2][16][132];
    __shared__ float sSum[128][17];

    const int bh = blockIdx.z;
    const int b  = bh / H_;
    const int q0 = blockIdx.y * 128;
    const int k0 = blockIdx.x * 128;
    const int t  = threadIdx.x;
    const int tq = t >> 4;          // 0..15 -> q rows  tq*8 .. tq*8+7
    const int tk = t & 15;          // 0..15 -> k cols  tk*8 .. tk*8+7

    const float* Qb = q + ((size_t)bh * S_ + q0) * D_;
    const float* Kb = k + ((size_t)bh * S_ + k0) * D_;

    // Load mapping: each thread loads rows lr0 and lr0+64 at d-offset ldd.
    const int ldd = (t & 3) * 4;
    const int lr0 = t >> 2;

    float4 qreg[2], kreg[2];
#pragma unroll
    for (int i = 0; i < 2; i++) {
        qreg[i] = *(const float4*)(Qb + (size_t)(lr0 + i * 64) * D_ + ldd);
        kreg[i] = *(const float4*)(Kb + (size_t)(lr0 + i * 64) * D_ + ldd);
    }
#pragma unroll
    for (int i = 0; i < 2; i++) {
        int row = lr0 + i * 64;
        sQ[0][ldd + 0][row] = qreg[i].x; sQ[0][ldd + 1][row] = qreg[i].y;
        sQ[0][ldd + 2][row] = qreg[i].z; sQ[0][ldd + 3][row] = qreg[i].w;
        sK[0][ldd + 0][row] = kreg[i].x; sK[0][ldd + 1][row] = kreg[i].y;
        sK[0][ldd + 2][row] = kreg[i].z; sK[0][ldd + 3][row] = kreg[i].w;
    }
    __syncthreads();

    float acc[8][8];
#pragma unroll
    for (int i = 0; i < 8; i++)
#pragma unroll
        for (int j = 0; j < 8; j++) acc[i][j] = 0.0f;

    int p = 0;
#pragma unroll
    for (int c = 0; c < 4; c++) {
        // Prefetch next chunk into registers while computing current.
        if (c < 3) {
            int d0 = (c + 1) * 16;
#pragma unroll
            for (int i = 0; i < 2; i++) {
                qreg[i] = *(const float4*)(Qb + (size_t)(lr0 + i * 64) * D_ + d0 + ldd);
                kreg[i] = *(const float4*)(Kb + (size_t)(lr0 + i * 64) * D_ + d0 + ldd);
            }
        }

#pragma unroll
        for (int dd = 0; dd < 16; dd++) {
            float4 a0 = *(const float4*)&sQ[p][dd][tq * 8];
            float4 a1 = *(const float4*)&sQ[p][dd][tq * 8 + 4];
            float4 b0 = *(const float4*)&sK[p][dd][tk * 8];
            float4 b1 = *(const float4*)&sK[p][dd][tk * 8 + 4];
            float av[8] = {a0.x, a0.y, a0.z, a0.w, a1.x, a1.y, a1.z, a1.w};
            float bv[8] = {b0.x, b0.y, b0.z, b0.w, b1.x, b1.y, b1.z, b1.w};
#pragma unroll
            for (int i = 0; i < 8; i++)
#pragma unroll
                for (int j = 0; j < 8; j++)
                    acc[i][j] = fmaf(av[i], bv[j], acc[i][j]);
        }

        if (c < 3) {
#pragma unroll
            for (int i = 0; i < 2; i++) {
                int row = lr0 + i * 64;
                sQ[p ^ 1][ldd + 0][row] = qreg[i].x; sQ[p ^ 1][ldd + 1][row] = qreg[i].y;
                sQ[p ^ 1][ldd + 2][row] = qreg[i].z; sQ[p ^ 1][ldd + 3][row] = qreg[i].w;
                sK[p ^ 1][ldd + 0][row] = kreg[i].x; sK[p ^ 1][ldd + 1][row] = kreg[i].y;
                sK[p ^ 1][ldd + 2][row] = kreg[i].z; sK[p ^ 1][ldd + 3][row] = kreg[i].w;
            }
        }
        __syncthreads();
        p ^= 1;
    }

    // Epilogue: mask -> exp (no max subtraction; logits are bounded), write E,
    // accumulate per-row partial sums.
#pragma unroll
    for (int i = 0; i < 8; i++) {
        int qq = q0 + tq * 8 + i;
        const int4* mp = (const int4*)(mask + ((size_t)b * S_ + qq) * S_ + k0 + tk * 8);
        float4* ap = (float4*)(attn + ((size_t)bh * S_ + qq) * S_ + k0 + tk * 8);
        int4 m0 = mp[0];
        int4 m1 = mp[1];
        float e0, e1, e2, e3, e4, e5, e6, e7;
        e0 = (m0.x == 0) ? 1.0f : __expf(acc[i][0] * SCALE_);
        e1 = (m0.y == 0) ? 1.0f : __expf(acc[i][1] * SCALE_);
        e2 = (m0.z == 0) ? 1.0f : __expf(acc[i][2] * SCALE_);
        e3 = (m0.w == 0) ? 1.0f : __expf(acc[i][3] * SCALE_);
        e4 = (m1.x == 0) ? 1.0f : __expf(acc[i][4] * SCALE_);
        e5 = (m1.y == 0) ? 1.0f : __expf(acc[i][5] * SCALE_);
        e6 = (m1.z == 0) ? 1.0f : __expf(acc[i][6] * SCALE_);
        e7 = (m1.w == 0) ? 1.0f : __expf(acc[i][7] * SCALE_);
        ap[0] = make_float4(e0, e1, e2, e3);
        ap[1] = make_float4(e4, e5, e6, e7);
        sSum[tq * 8 + i][tk] = ((e0 + e1) + (e2 + e3)) + ((e4 + e5) + (e6 + e7));
    }
    __syncthreads();

    if (t < 128) {
        float s = 0.0f;
#pragma unroll
        for (int j = 0; j < 16; j++) s += sSum[t][j];
        atomicAdd(&g_rowsum[(size_t)bh * S_ + q0 + t], s);
    }
}

// ---------------------------------------------------------------------------
// Kernel 2: fused normalize + AV.
// Block owns 256 q-rows; streams E in 256x32 chunks: normalizes (E/rowsum),
// writes probs in place, and accumulates O = P @ V.
// 256 threads, 8x8 per-thread register tile over a 256x64 C-tile.
// ---------------------------------------------------------------------------
__global__ __launch_bounds__(256, 2)
void norm_av_kernel(float* __restrict__ attn, const float* __restrict__ v,
                    float* __restrict__ out)
{
    __shared__ float sP[32][260];   // [k][q-row], transposed
    __shared__ float sV[32][64];    // [k][d]
    __shared__ float sInv[256];

    const int bh = blockIdx.y;
    const int q0 = blockIdx.x * 256;
    const int t  = threadIdx.x;
    const int tq = t >> 3;          // 0..31 -> q rows tq*8..
    const int td = t & 7;           // 0..7  -> d cols td*8..

    float* Pb = attn + ((size_t)bh * S_ + q0) * S_;
    const float* Vb = v + (size_t)bh * S_ * D_;

    sInv[t] = 1.0f / g_rowsum[(size_t)bh * S_ + q0 + t];
    __syncthreads();

    float acc[8][8];
#pragma unroll
    for (int i = 0; i < 8; i++)
#pragma unroll
        for (int j = 0; j < 8; j++) acc[i][j] = 0.0f;

    for (int c0 = 0; c0 < S_; c0 += 32) {
        // E chunk 256x32 = 2048 float4; 8 per thread.
        // Normalize, write back to gmem (in place), store transposed to smem.
#pragma unroll
        for (int i = 0; i < 8; i++) {
            int vid = t + i * 256;
            int row = vid >> 3;          // 0..255
            int c4  = (vid & 7) * 4;     // 0..28
            float4* gp = (float4*)(Pb + (size_t)row * S_ + c0 + c4);
            float4 e = *gp;
            float inv = sInv[row];
            e.x *= inv; e.y *= inv; e.z *= inv; e.w *= inv;
            *gp = e;
            sP[c4 + 0][row] = e.x; sP[c4 + 1][row] = e.y;
            sP[c4 + 2][row] = e.z; sP[c4 + 3][row] = e.w;
        }
        // V chunk 32x64 = 512 float4; 2 per thread.
#pragma unroll
        for (int i = 0; i < 2; i++) {
            int vid = t + i * 256;
            int row = vid >> 4;          // 0..31
            int c4  = (vid & 15) * 4;    // 0..60
            *(float4*)&sV[row][c4] =
                *(const float4*)(Vb + (size_t)(c0 + row) * D_ + c4);
        }
        __syncthreads();

#pragma unroll
        for (int kk = 0; kk < 32; kk++) {
            float4 a0 = *(const float4*)&sP[kk][tq * 8];
            float4 a1 = *(const float4*)&sP[kk][tq * 8 + 4];
            float4 b0 = *(const float4*)&sV[kk][td * 8];
            float4 b1 = *(const float4*)&sV[kk][td * 8 + 4];
            float av[8] = {a0.x, a0.y, a0.z, a0.w, a1.x, a1.y, a1.z, a1.w};
            float bv[8] = {b0.x, b0.y, b0.z, b0.w, b1.x, b1.y, b1.z, b1.w};
#pragma unroll
            for (int i = 0; i < 8; i++)
#pragma unroll
                for (int j = 0; j < 8; j++)
                    acc[i][j] = fmaf(av[i], bv[j], acc[i][j]);
        }
        __syncthreads();
    }

#pragma unroll
    for (int i = 0; i < 8; i++) {
        int qq = q0 + tq * 8 + i;
        float4* op = (float4*)(out + ((size_t)bh * S_ + qq) * D_ + td * 8);
        op[0] = make_float4(acc[i][0], acc[i][1], acc[i][2], acc[i][3]);
        op[1] = make_float4(acc[i][4], acc[i][5], acc[i][6], acc[i][7]);
    }
}

// ---------------------------------------------------------------------------
// Launch: out buffer = [output (B,H,S,D) | attention (B,H,S,S)]
// ---------------------------------------------------------------------------
extern "C" void kernel_launch(void* const* d_in, const int* in_sizes, int n_in,
                              void* d_out, int out_size)
{
    const float* q    = (const float*)d_in[0];
    const float* k    = (const float*)d_in[1];
    const float* v    = (const float*)d_in[2];
    const int*   mask = (const int*)d_in[3];

    float* out  = (float*)d_out;
    float* attn = out + (size_t)BH_ * S_ * D_;

    zero_rowsum_kernel<<<(BH_ * S_) / 256, 256>>>();

    dim3 g1(S_ / 128, S_ / 128, BH_);
    qk_exp_kernel<<<g1, 256>>>(q, k, mask, attn);

    dim3 g2(S_ / 256, BH_);
    norm_av_kernel<<<g2, 256>>>(attn, v, out);
}

// round 4
// speedup vs baseline: 1.0114x; 1.0114x over previous
#include <cuda_runtime.h>

#define B_  2
#define H_  12
#define S_  2048
#define D_  64
#define BH_ (B_ * H_)
#define SCALE_ 0.125f   // 1/sqrt(64)

// Per-row sums of unnormalized exp(logit). 24*2048 floats.
__device__ float g_rowsum[BH_ * S_];

// ---------------------------------------------------------------------------
// Kernel 0: zero the rowsum accumulator.
// ---------------------------------------------------------------------------
__global__ void zero_rowsum_kernel()
{
    g_rowsum[blockIdx.x * 256 + threadIdx.x] = 0.0f;
}

// ---------------------------------------------------------------------------
// Kernel 1: QK^T + mask + exp (unnormalized), rowsum accumulation.
// C-tile 128x128, 256 threads, 8x8 per-thread register tile.
// Double-buffered d-chunks of 16. Writes E = exp(masked logit) to attn region.
// ---------------------------------------------------------------------------
__global__ __launch_bounds__(256, 2)
void qk_exp_kernel(const float* __restrict__ q, const float* __restrict__ k,
                   const int* __restrict__ mask, float* __restrict__ attn)
{
    __shared__ float sQ[2][16][132];
    __shared__ float sK[2][16][132];
    __shared__ float sSum[128][17];

    const int bh = blockIdx.z;
    const int b  = bh / H_;
    const int q0 = blockIdx.y * 128;
    const int k0 = blockIdx.x * 128;
    const int t  = threadIdx.x;
    const int tq = t >> 4;          // 0..15 -> q rows  tq*8 .. tq*8+7
    const int tk = t & 15;          // 0..15 -> k cols  tk*8 .. tk*8+7

    const float* Qb = q + ((size_t)bh * S_ + q0) * D_;
    const float* Kb = k + ((size_t)bh * S_ + k0) * D_;

    // Load mapping: each thread loads rows lr0 and lr0+64 at d-offset ldd.
    const int ldd = (t & 3) * 4;
    const int lr0 = t >> 2;

    float4 qreg[2], kreg[2];
#pragma unroll
    for (int i = 0; i < 2; i++) {
        qreg[i] = *(const float4*)(Qb + (size_t)(lr0 + i * 64) * D_ + ldd);
        kreg[i] = *(const float4*)(Kb + (size_t)(lr0 + i * 64) * D_ + ldd);
    }
#pragma unroll
    for (int i = 0; i < 2; i++) {
        int row = lr0 + i * 64;
        sQ[0][ldd + 0][row] = qreg[i].x; sQ[0][ldd + 1][row] = qreg[i].y;
        sQ[0][ldd + 2][row] = qreg[i].z; sQ[0][ldd + 3][row] = qreg[i].w;
        sK[0][ldd + 0][row] = kreg[i].x; sK[0][ldd + 1][row] = kreg[i].y;
        sK[0][ldd + 2][row] = kreg[i].z; sK[0][ldd + 3][row] = kreg[i].w;
    }
    __syncthreads();

    float acc[8][8];
#pragma unroll
    for (int i = 0; i < 8; i++)
#pragma unroll
        for (int j = 0; j < 8; j++) acc[i][j] = 0.0f;

    int p = 0;
#pragma unroll
    for (int c = 0; c < 4; c++) {
        // Prefetch next chunk into registers while computing current.
        if (c < 3) {
            int d0 = (c + 1) * 16;
#pragma unroll
            for (int i = 0; i < 2; i++) {
                qreg[i] = *(const float4*)(Qb + (size_t)(lr0 + i * 64) * D_ + d0 + ldd);
                kreg[i] = *(const float4*)(Kb + (size_t)(lr0 + i * 64) * D_ + d0 + ldd);
            }
        }

#pragma unroll
        for (int dd = 0; dd < 16; dd++) {
            float4 a0 = *(const float4*)&sQ[p][dd][tq * 8];
            float4 a1 = *(const float4*)&sQ[p][dd][tq * 8 + 4];
            float4 b0 = *(const float4*)&sK[p][dd][tk * 8];
            float4 b1 = *(const float4*)&sK[p][dd][tk * 8 + 4];
            float av[8] = {a0.x, a0.y, a0.z, a0.w, a1.x, a1.y, a1.z, a1.w};
            float bv[8] = {b0.x, b0.y, b0.z, b0.w, b1.x, b1.y, b1.z, b1.w};
#pragma unroll
            for (int i = 0; i < 8; i++)
#pragma unroll
                for (int j = 0; j < 8; j++)
                    acc[i][j] = fmaf(av[i], bv[j], acc[i][j]);
        }

        if (c < 3) {
#pragma unroll
            for (int i = 0; i < 2; i++) {
                int row = lr0 + i * 64;
                sQ[p ^ 1][ldd + 0][row] = qreg[i].x; sQ[p ^ 1][ldd + 1][row] = qreg[i].y;
                sQ[p ^ 1][ldd + 2][row] = qreg[i].z; sQ[p ^ 1][ldd + 3][row] = qreg[i].w;
                sK[p ^ 1][ldd + 0][row] = kreg[i].x; sK[p ^ 1][ldd + 1][row] = kreg[i].y;
                sK[p ^ 1][ldd + 2][row] = kreg[i].z; sK[p ^ 1][ldd + 3][row] = kreg[i].w;
            }
        }
        __syncthreads();
        p ^= 1;
    }

    // Epilogue: mask -> exp (no max subtraction; logits are bounded), write E,
    // accumulate per-row partial sums.
#pragma unroll
    for (int i = 0; i < 8; i++) {
        int qq = q0 + tq * 8 + i;
        const int4* mp = (const int4*)(mask + ((size_t)b * S_ + qq) * S_ + k0 + tk * 8);
        float4* ap = (float4*)(attn + ((size_t)bh * S_ + qq) * S_ + k0 + tk * 8);
        int4 m0 = mp[0];
        int4 m1 = mp[1];
        float e0, e1, e2, e3, e4, e5, e6, e7;
        e0 = (m0.x == 0) ? 1.0f : __expf(acc[i][0] * SCALE_);
        e1 = (m0.y == 0) ? 1.0f : __expf(acc[i][1] * SCALE_);
        e2 = (m0.z == 0) ? 1.0f : __expf(acc[i][2] * SCALE_);
        e3 = (m0.w == 0) ? 1.0f : __expf(acc[i][3] * SCALE_);
        e4 = (m1.x == 0) ? 1.0f : __expf(acc[i][4] * SCALE_);
        e5 = (m1.y == 0) ? 1.0f : __expf(acc[i][5] * SCALE_);
        e6 = (m1.z == 0) ? 1.0f : __expf(acc[i][6] * SCALE_);
        e7 = (m1.w == 0) ? 1.0f : __expf(acc[i][7] * SCALE_);
        ap[0] = make_float4(e0, e1, e2, e3);
        ap[1] = make_float4(e4, e5, e6, e7);
        sSum[tq * 8 + i][tk] = ((e0 + e1) + (e2 + e3)) + ((e4 + e5) + (e6 + e7));
    }
    __syncthreads();

    if (t < 128) {
        float s = 0.0f;
#pragma unroll
        for (int j = 0; j < 16; j++) s += sSum[t][j];
        atomicAdd(&g_rowsum[(size_t)bh * S_ + q0 + t], s);
    }
}

// ---------------------------------------------------------------------------
// Kernel 2: fused normalize + AV.
// Block owns 128 q-rows; streams E in 128x32 chunks: normalizes (E/rowsum),
// writes probs in place, and accumulates O = P @ V.
// 256 threads, 4x8 per-thread register tile over a 128x64 C-tile.
// Grid 384, ~64 regs -> 4 CTAs/SM for wave smoothing.
// ---------------------------------------------------------------------------
__global__ __launch_bounds__(256, 4)
void norm_av_kernel(float* __restrict__ attn, const float* __restrict__ v,
                    float* __restrict__ out)
{
    __shared__ float sP[32][132];   // [k][q-row], transposed
    __shared__ float sV[32][64];    // [k][d]
    __shared__ float sInv[128];

    const int bh = blockIdx.y;
    const int q0 = blockIdx.x * 128;
    const int t  = threadIdx.x;
    const int tq = t >> 3;          // 0..31 -> q rows tq*4 .. tq*4+3
    const int td = t & 7;           // 0..7  -> d cols td*8 .. td*8+7

    float* Pb = attn + ((size_t)bh * S_ + q0) * S_;
    const float* Vb = v + (size_t)bh * S_ * D_;

    if (t < 128)
        sInv[t] = 1.0f / g_rowsum[(size_t)bh * S_ + q0 + t];
    __syncthreads();

    float acc[4][8];
#pragma unroll
    for (int i = 0; i < 4; i++)
#pragma unroll
        for (int j = 0; j < 8; j++) acc[i][j] = 0.0f;

    for (int c0 = 0; c0 < S_; c0 += 32) {
        // E chunk 128x32 = 1024 float4; 4 per thread.
        // Normalize, write back to gmem (in place), store transposed to smem.
#pragma unroll
        for (int i = 0; i < 4; i++) {
            int vid = t + i * 256;
            int row = vid >> 3;          // 0..127
            int c4  = (vid & 7) * 4;     // 0..28
            float4* gp = (float4*)(Pb + (size_t)row * S_ + c0 + c4);
            float4 e = *gp;
            float inv = sInv[row];
            e.x *= inv; e.y *= inv; e.z *= inv; e.w *= inv;
            *gp = e;
            sP[c4 + 0][row] = e.x; sP[c4 + 1][row] = e.y;
            sP[c4 + 2][row] = e.z; sP[c4 + 3][row] = e.w;
        }
        // V chunk 32x64 = 512 float4; 2 per thread.
#pragma unroll
        for (int i = 0; i < 2; i++) {
            int vid = t + i * 256;
            int row = vid >> 4;          // 0..31
            int c4  = (vid & 15) * 4;    // 0..60
            *(float4*)&sV[row][c4] =
                *(const float4*)(Vb + (size_t)(c0 + row) * D_ + c4);
        }
        __syncthreads();

#pragma unroll
        for (int kk = 0; kk < 32; kk++) {
            float4 a0 = *(const float4*)&sP[kk][tq * 4];
            float4 b0 = *(const float4*)&sV[kk][td * 8];
            float4 b1 = *(const float4*)&sV[kk][td * 8 + 4];
            float av[4] = {a0.x, a0.y, a0.z, a0.w};
            float bv[8] = {b0.x, b0.y, b0.z, b0.w, b1.x, b1.y, b1.z, b1.w};
#pragma unroll
            for (int i = 0; i < 4; i++)
#pragma unroll
                for (int j = 0; j < 8; j++)
                    acc[i][j] = fmaf(av[i], bv[j], acc[i][j]);
        }
        __syncthreads();
    }

#pragma unroll
    for (int i = 0; i < 4; i++) {
        int qq = q0 + tq * 4 + i;
        float4* op = (float4*)(out + ((size_t)bh * S_ + qq) * D_ + td * 8);
        op[0] = make_float4(acc[i][0], acc[i][1], acc[i][2], acc[i][3]);
        op[1] = make_float4(acc[i][4], acc[i][5], acc[i][6], acc[i][7]);
    }
}

// ---------------------------------------------------------------------------
// Launch: out buffer = [output (B,H,S,D) | attention (B,H,S,S)]
// ---------------------------------------------------------------------------
extern "C" void kernel_launch(void* const* d_in, const int* in_sizes, int n_in,
                              void* d_out, int out_size)
{
    const float* q    = (const float*)d_in[0];
    const float* k    = (const float*)d_in[1];
    const float* v    = (const float*)d_in[2];
    const int*   mask = (const int*)d_in[3];

    float* out  = (float*)d_out;
    float* attn = out + (size_t)BH_ * S_ * D_;

    zero_rowsum_kernel<<<(BH_ * S_) / 256, 256>>>();

    dim3 g1(S_ / 128, S_ / 128, BH_);
    qk_exp_kernel<<<g1, 256>>>(q, k, mask, attn);

    dim3 g2(S_ / 128, BH_);
    norm_av_kernel<<<g2, 256>>>(attn, v, out);
}

// round 10
// speedup vs baseline: 1.0379x; 1.0262x over previous
#include <cuda_runtime.h>

#define B_  2
#define H_  12
#define S_  2048
#define D_  64
#define BH_ (B_ * H_)
#define SCALE_ 0.125f   // 1/sqrt(64)

// ---------------------------------------------------------------------------
// Kernel 1: QK^T logits with mask epilogue. Double-buffered.
// C-tile 128x128, 256 threads, 8x8 per-thread register tile.
// ---------------------------------------------------------------------------
__global__ __launch_bounds__(256, 2)
void qk_kernel(const float* __restrict__ q, const float* __restrict__ k,
               const int* __restrict__ mask, float* __restrict__ attn)
{
    __shared__ float sQ[2][16][132];
    __shared__ float sK[2][16][132];

    const int bh = blockIdx.z;
    const int b  = bh / H_;
    const int q0 = blockIdx.y * 128;
    const int k0 = blockIdx.x * 128;
    const int t  = threadIdx.x;
    const int tq = t >> 4;          // 0..15 -> q rows  tq*8 .. tq*8+7
    const int tk = t & 15;          // 0..15 -> k cols  tk*8 .. tk*8+7

    const float* Qb = q + ((size_t)bh * S_ + q0) * D_;
    const float* Kb = k + ((size_t)bh * S_ + k0) * D_;

    // Load mapping: each thread loads rows lr0 and lr0+64 at d-offset ldd.
    const int ldd = (t & 3) * 4;
    const int lr0 = t >> 2;

    float4 qreg[2], kreg[2];
#pragma unroll
    for (int i = 0; i < 2; i++) {
        qreg[i] = *(const float4*)(Qb + (size_t)(lr0 + i * 64) * D_ + ldd);
        kreg[i] = *(const float4*)(Kb + (size_t)(lr0 + i * 64) * D_ + ldd);
    }
#pragma unroll
    for (int i = 0; i < 2; i++) {
        int row = lr0 + i * 64;
        sQ[0][ldd + 0][row] = qreg[i].x; sQ[0][ldd + 1][row] = qreg[i].y;
        sQ[0][ldd + 2][row] = qreg[i].z; sQ[0][ldd + 3][row] = qreg[i].w;
        sK[0][ldd + 0][row] = kreg[i].x; sK[0][ldd + 1][row] = kreg[i].y;
        sK[0][ldd + 2][row] = kreg[i].z; sK[0][ldd + 3][row] = kreg[i].w;
    }
    __syncthreads();

    float acc[8][8];
#pragma unroll
    for (int i = 0; i < 8; i++)
#pragma unroll
        for (int j = 0; j < 8; j++) acc[i][j] = 0.0f;

    int p = 0;
#pragma unroll
    for (int c = 0; c < 4; c++) {
        if (c < 3) {
            int d0 = (c + 1) * 16;
#pragma unroll
            for (int i = 0; i < 2; i++) {
                qreg[i] = *(const float4*)(Qb + (size_t)(lr0 + i * 64) * D_ + d0 + ldd);
                kreg[i] = *(const float4*)(Kb + (size_t)(lr0 + i * 64) * D_ + d0 + ldd);
            }
        }

#pragma unroll
        for (int dd = 0; dd < 16; dd++) {
            float4 a0 = *(const float4*)&sQ[p][dd][tq * 8];
            float4 a1 = *(const float4*)&sQ[p][dd][tq * 8 + 4];
            float4 b0 = *(const float4*)&sK[p][dd][tk * 8];
            float4 b1 = *(const float4*)&sK[p][dd][tk * 8 + 4];
            float av[8] = {a0.x, a0.y, a0.z, a0.w, a1.x, a1.y, a1.z, a1.w};
            float bv[8] = {b0.x, b0.y, b0.z, b0.w, b1.x, b1.y, b1.z, b1.w};
#pragma unroll
            for (int i = 0; i < 8; i++)
#pragma unroll
                for (int j = 0; j < 8; j++)
                    acc[i][j] = fmaf(av[i], bv[j], acc[i][j]);
        }

        if (c < 3) {
#pragma unroll
            for (int i = 0; i < 2; i++) {
                int row = lr0 + i * 64;
                sQ[p ^ 1][ldd + 0][row] = qreg[i].x; sQ[p ^ 1][ldd + 1][row] = qreg[i].y;
                sQ[p ^ 1][ldd + 2][row] = qreg[i].z; sQ[p ^ 1][ldd + 3][row] = qreg[i].w;
                sK[p ^ 1][ldd + 0][row] = kreg[i].x; sK[p ^ 1][ldd + 1][row] = kreg[i].y;
                sK[p ^ 1][ldd + 2][row] = kreg[i].z; sK[p ^ 1][ldd + 3][row] = kreg[i].w;
            }
            __syncthreads();
        }
        p ^= 1;
    }

    // Epilogue: scale + mask (mask==0 -> 1e-9), write raw masked logits.
#pragma unroll
    for (int i = 0; i < 8; i++) {
        int qq = q0 + tq * 8 + i;
        const int4* mp = (const int4*)(mask + ((size_t)b * S_ + qq) * S_ + k0 + tk * 8);
        float4* ap = (float4*)(attn + ((size_t)bh * S_ + qq) * S_ + k0 + tk * 8);
        int4 m0 = mp[0];
        int4 m1 = mp[1];
        float4 r0, r1;
        r0.x = (m0.x == 0) ? 1e-9f : acc[i][0] * SCALE_;
        r0.y = (m0.y == 0) ? 1e-9f : acc[i][1] * SCALE_;
        r0.z = (m0.z == 0) ? 1e-9f : acc[i][2] * SCALE_;
        r0.w = (m0.w == 0) ? 1e-9f : acc[i][3] * SCALE_;
        r1.x = (m1.x == 0) ? 1e-9f : acc[i][4] * SCALE_;
        r1.y = (m1.y == 0) ? 1e-9f : acc[i][5] * SCALE_;
        r1.z = (m1.z == 0) ? 1e-9f : acc[i][6] * SCALE_;
        r1.w = (m1.w == 0) ? 1e-9f : acc[i][7] * SCALE_;
        ap[0] = r0;
        ap[1] = r1;
    }
}

// ---------------------------------------------------------------------------
// Kernel 2: in-place row softmax over the attention region.
// One block (256 threads) per row of 2048; 8 elements/thread in registers.
// ---------------------------------------------------------------------------
__global__ __launch_bounds__(256)
void softmax_kernel(float* __restrict__ attn)
{
    __shared__ float smax[8];
    __shared__ float ssum[8];

    const size_t row = blockIdx.x;          // bh*S + q
    float* p = attn + row * S_;
    const int t    = threadIdx.x;
    const int wid  = t >> 5;
    const int lane = t & 31;

    float4 v0 = ((const float4*)p)[t];
    float4 v1 = ((const float4*)p)[t + 256];

    float m = fmaxf(fmaxf(fmaxf(v0.x, v0.y), fmaxf(v0.z, v0.w)),
                    fmaxf(fmaxf(v1.x, v1.y), fmaxf(v1.z, v1.w)));
#pragma unroll
    for (int o = 16; o > 0; o >>= 1)
        m = fmaxf(m, __shfl_xor_sync(0xffffffffu, m, o));
    if (lane == 0) smax[wid] = m;
    __syncthreads();
    float mr = smax[0];
#pragma unroll
    for (int i = 1; i < 8; i++) mr = fmaxf(mr, smax[i]);

    float e0x = __expf(v0.x - mr), e0y = __expf(v0.y - mr);
    float e0z = __expf(v0.z - mr), e0w = __expf(v0.w - mr);
    float e1x = __expf(v1.x - mr), e1y = __expf(v1.y - mr);
    float e1z = __expf(v1.z - mr), e1w = __expf(v1.w - mr);

    float s = ((e0x + e0y) + (e0z + e0w)) + ((e1x + e1y) + (e1z + e1w));
#pragma unroll
    for (int o = 16; o > 0; o >>= 1)
        s += __shfl_xor_sync(0xffffffffu, s, o);
    if (lane == 0) ssum[wid] = s;
    __syncthreads();
    float total = ssum[0];
#pragma unroll
    for (int i = 1; i < 8; i++) total += ssum[i];

    float inv = 1.0f / total;
    float4 r0 = make_float4(e0x * inv, e0y * inv, e0z * inv, e0w * inv);
    float4 r1 = make_float4(e1x * inv, e1y * inv, e1z * inv, e1w * inv);
    ((float4*)p)[t]       = r0;
    ((float4*)p)[t + 256] = r1;
}

// ---------------------------------------------------------------------------
// Kernel 3: output = P @ V. Double-buffered.
// C-tile 64x64, 128 threads, 4x8 per-thread register tile, k-chunks of 32.
// ---------------------------------------------------------------------------
__global__ __launch_bounds__(128, 4)
void av_kernel(const float* __restrict__ attn, const float* __restrict__ v,
               float* __restrict__ out)
{
    __shared__ float sP[2][32][68];   // [k][q-row], transposed, pad 68
    __shared__ float sV[2][32][64];   // [k][d]

    const int bh = blockIdx.y;
    const int q0 = blockIdx.x * 64;
    const int t  = threadIdx.x;
    const int tq = t >> 3;          // 0..15 -> q rows tq*4 .. tq*4+3
    const int td = t & 7;           // 0..7  -> d cols td*8 .. td*8+7

    const float* Pb = attn + ((size_t)bh * S_ + q0) * S_;
    const float* Vb = v + (size_t)bh * S_ * D_;

    // Load mappings.
    const int prow = t >> 3;            // 0..15 (with i offset -> 0..63)
    const int pc4  = (t & 7) * 4;       // 0..28
    const int vrow = t >> 4;            // 0..7  (with i offset -> 0..31)
    const int vc4  = (t & 15) * 4;      // 0..60

    float4 preg[4], vreg[4];

    // Preload chunk 0. P: 64x32 = 512 float4, 4/thread. V: 32x64 = 512 float4, 4/thread.
#pragma unroll
    for (int i = 0; i < 4; i++)
        preg[i] = *(const float4*)(Pb + (size_t)(prow + i * 16) * S_ + pc4);
#pragma unroll
    for (int i = 0; i < 4; i++)
        vreg[i] = *(const float4*)(Vb + (size_t)(vrow + i * 8) * D_ + vc4);

#pragma unroll
    for (int i = 0; i < 4; i++) {
        int row = prow + i * 16;
        sP[0][pc4 + 0][row] = preg[i].x; sP[0][pc4 + 1][row] = preg[i].y;
        sP[0][pc4 + 2][row] = preg[i].z; sP[0][pc4 + 3][row] = preg[i].w;
    }
#pragma unroll
    for (int i = 0; i < 4; i++)
        *(float4*)&sV[0][vrow + i * 8][vc4] = vreg[i];
    __syncthreads();

    float acc[4][8];
#pragma unroll
    for (int i = 0; i < 4; i++)
#pragma unroll
        for (int j = 0; j < 8; j++) acc[i][j] = 0.0f;

    int p = 0;
    for (int c0 = 0; c0 < S_; c0 += 32) {
        if (c0 + 32 < S_) {
#pragma unroll
            for (int i = 0; i < 4; i++)
                preg[i] = *(const float4*)(Pb + (size_t)(prow + i * 16) * S_ + c0 + 32 + pc4);
#pragma unroll
            for (int i = 0; i < 4; i++)
                vreg[i] = *(const float4*)(Vb + (size_t)(c0 + 32 + vrow + i * 8) * D_ + vc4);
        }

#pragma unroll
        for (int kk = 0; kk < 32; kk++) {
            float4 a0 = *(const float4*)&sP[p][kk][tq * 4];
            float4 b0 = *(const float4*)&sV[p][kk][td * 8];
            float4 b1 = *(const float4*)&sV[p][kk][td * 8 + 4];
            float av[4] = {a0.x, a0.y, a0.z, a0.w};
            float bv[8] = {b0.x, b0.y, b0.z, b0.w, b1.x, b1.y, b1.z, b1.w};
#pragma unroll
            for (int i = 0; i < 4; i++)
#pragma unroll
                for (int j = 0; j < 8; j++)
                    acc[i][j] = fmaf(av[i], bv[j], acc[i][j]);
        }

        if (c0 + 32 < S_) {
#pragma unroll
            for (int i = 0; i < 4; i++) {
                int row = prow + i * 16;
                sP[p ^ 1][pc4 + 0][row] = preg[i].x; sP[p ^ 1][pc4 + 1][row] = preg[i].y;
                sP[p ^ 1][pc4 + 2][row] = preg[i].z; sP[p ^ 1][pc4 + 3][row] = preg[i].w;
            }
#pragma unroll
            for (int i = 0; i < 4; i++)
                *(float4*)&sV[p ^ 1][vrow + i * 8][vc4] = vreg[i];
            __syncthreads();
        }
        p ^= 1;
    }

#pragma unroll
    for (int i = 0; i < 4; i++) {
        int qq = q0 + tq * 4 + i;
        float4* op = (float4*)(out + ((size_t)bh * S_ + qq) * D_ + td * 8);
        op[0] = make_float4(acc[i][0], acc[i][1], acc[i][2], acc[i][3]);
        op[1] = make_float4(acc[i][4], acc[i][5], acc[i][6], acc[i][7]);
    }
}

// ---------------------------------------------------------------------------
// Launch: out buffer = [output (B,H,S,D) | attention (B,H,S,S)]
// ---------------------------------------------------------------------------
extern "C" void kernel_launch(void* const* d_in, const int* in_sizes, int n_in,
                              void* d_out, int out_size)
{
    const float* q    = (const float*)d_in[0];
    const float* k    = (const float*)d_in[1];
    const float* v    = (const float*)d_in[2];
    const int*   mask = (const int*)d_in[3];

    float* out  = (float*)d_out;
    float* attn = out + (size_t)BH_ * S_ * D_;

    dim3 g1(S_ / 128, S_ / 128, BH_);
    qk_kernel<<<g1, 256>>>(q, k, mask, attn);

    softmax_kernel<<<(unsigned)(BH_ * S_), 256>>>(attn);

    dim3 g3(S_ / 64, BH_);
    av_kernel<<<g3, 128>>>(attn, v, out);
}

// round 11
// speedup vs baseline: 1.3976x; 1.3466x over previous
#include <cuda_runtime.h>
#include <cstdint>

#define B_  2
#define H_  12
#define S_  2048
#define D_  64
#define BH_ (B_ * H_)
#define SCALE_ 0.125f   // 1/sqrt(64)

#define QK_PAD 68       // stride ≡ 4 (mod 32) -> conflict-free fragment LDS
#define QK_SMEM_BYTES (2 * 128 * QK_PAD * 4)

// ---------------------------------------------------------------------------
// tf32 helpers
// ---------------------------------------------------------------------------
__device__ __forceinline__ uint32_t f2tf32(float x)
{
    uint32_t r;
    asm("cvt.rna.tf32.f32 %0, %1;" : "=r"(r) : "f"(x));
    return r;
}

__device__ __forceinline__ void split_tf32(float x, uint32_t& hi, uint32_t& lo)
{
    hi = f2tf32(x);
    lo = f2tf32(x - __uint_as_float(hi));
}

__device__ __forceinline__ void mma_tf32(float* c, const uint32_t* a, const uint32_t* b)
{
    asm("mma.sync.aligned.m16n8k8.row.col.f32.tf32.tf32.f32 "
        "{%0,%1,%2,%3}, {%4,%5,%6,%7}, {%8,%9}, {%0,%1,%2,%3};"
        : "+f"(c[0]), "+f"(c[1]), "+f"(c[2]), "+f"(c[3])
        : "r"(a[0]), "r"(a[1]), "r"(a[2]), "r"(a[3]), "r"(b[0]), "r"(b[1]));
}

// ---------------------------------------------------------------------------
// Kernel 1: QK^T via 3xTF32 tensor-core MMA + mask epilogue.
// C-tile 128x128, 256 threads (8 warps, 4m x 2n), warp tile 32m x 64n.
// Q,K tiles in smem as fp32 [row][k] stride 68; hi/lo split on the fly.
// ---------------------------------------------------------------------------
__global__ __launch_bounds__(256)
void qk_tf32_kernel(const float* __restrict__ q, const float* __restrict__ k,
                    const int* __restrict__ mask, float* __restrict__ attn)
{
    extern __shared__ float smem[];
    float* sQ = smem;                 // [128][QK_PAD]
    float* sK = smem + 128 * QK_PAD;  // [128][QK_PAD]

    const int bh = blockIdx.z;
    const int b  = bh / H_;
    const int q0 = blockIdx.y * 128;
    const int k0 = blockIdx.x * 128;
    const int t    = threadIdx.x;
    const int lane = t & 31;
    const int wid  = t >> 5;
    const int wm   = wid >> 1;        // 0..3 -> q rows [wm*32, +32)
    const int wn   = wid & 1;         // 0..1 -> k cols [wn*64, +64)
    const int g    = lane >> 2;       // groupID 0..7
    const int tg   = lane & 3;        // thread-in-group 0..3

    const float* Qb = q + ((size_t)bh * S_ + q0) * D_;
    const float* Kb = k + ((size_t)bh * S_ + k0) * D_;

    // Load Q and K tiles (128x64 fp32 each): 2048 float4 per tile, 8/thread.
#pragma unroll
    for (int i = 0; i < 8; i++) {
        int vid = t + i * 256;
        int row = vid >> 4;           // 0..127
        int c4  = (vid & 15) * 4;     // 0..60
        *(float4*)&sQ[row * QK_PAD + c4] = *(const float4*)(Qb + (size_t)row * D_ + c4);
        *(float4*)&sK[row * QK_PAD + c4] = *(const float4*)(Kb + (size_t)row * D_ + c4);
    }
    __syncthreads();

    float acc[2][8][4];               // [mt][nt][reg]
#pragma unroll
    for (int mt = 0; mt < 2; mt++)
#pragma unroll
        for (int nt = 0; nt < 8; nt++)
#pragma unroll
            for (int r = 0; r < 4; r++) acc[mt][nt][r] = 0.0f;

#pragma unroll
    for (int ks = 0; ks < 8; ks++) {
        const int kb = ks * 8 + tg;

        // A fragments (2 m-tiles): a0=(g,kb) a1=(g+8,kb) a2=(g,kb+4) a3=(g+8,kb+4)
        uint32_t ahi[2][4], alo[2][4];
#pragma unroll
        for (int mt = 0; mt < 2; mt++) {
            int r = wm * 32 + mt * 16 + g;
            split_tf32(sQ[r * QK_PAD + kb],           ahi[mt][0], alo[mt][0]);
            split_tf32(sQ[(r + 8) * QK_PAD + kb],     ahi[mt][1], alo[mt][1]);
            split_tf32(sQ[r * QK_PAD + kb + 4],       ahi[mt][2], alo[mt][2]);
            split_tf32(sQ[(r + 8) * QK_PAD + kb + 4], ahi[mt][3], alo[mt][3]);
        }

        // B fragments (8 n-tiles): b0=(k=tg, n=g) b1=(k=tg+4, n=g); B[n][k]=sK[col][k]
        uint32_t bhi[8][2], blo[8][2];
#pragma unroll
        for (int nt = 0; nt < 8; nt++) {
            int cc = wn * 64 + nt * 8 + g;
            split_tf32(sK[cc * QK_PAD + kb],     bhi[nt][0], blo[nt][0]);
            split_tf32(sK[cc * QK_PAD + kb + 4], bhi[nt][1], blo[nt][1]);
        }

        // 3xTF32: hi*hi + hi*lo + lo*hi
#pragma unroll
        for (int mt = 0; mt < 2; mt++)
#pragma unroll
            for (int nt = 0; nt < 8; nt++) {
                mma_tf32(acc[mt][nt], ahi[mt], bhi[nt]);
                mma_tf32(acc[mt][nt], ahi[mt], blo[nt]);
                mma_tf32(acc[mt][nt], alo[mt], bhi[nt]);
            }
    }

    // Epilogue: scale + mask, write raw masked logits.
    // C layout: regs {0,1} -> row g, cols 2tg,2tg+1; regs {2,3} -> row g+8.
#pragma unroll
    for (int mt = 0; mt < 2; mt++)
#pragma unroll
        for (int nt = 0; nt < 8; nt++)
#pragma unroll
            for (int rr = 0; rr < 2; rr++) {
                int qq = q0 + wm * 32 + mt * 16 + g + 8 * rr;
                int kc = k0 + wn * 64 + nt * 8 + 2 * tg;
                int2 m2 = *(const int2*)(mask + ((size_t)b * S_ + qq) * S_ + kc);
                float2 r;
                r.x = (m2.x == 0) ? 1e-9f : acc[mt][nt][2 * rr + 0] * SCALE_;
                r.y = (m2.y == 0) ? 1e-9f : acc[mt][nt][2 * rr + 1] * SCALE_;
                *(float2*)(attn + ((size_t)bh * S_ + qq) * S_ + kc) = r;
            }
}

// ---------------------------------------------------------------------------
// Kernel 2: in-place row softmax over the attention region. (R2, verified)
// ---------------------------------------------------------------------------
__global__ __launch_bounds__(256)
void softmax_kernel(float* __restrict__ attn)
{
    __shared__ float smax[8];
    __shared__ float ssum[8];

    const size_t row = blockIdx.x;          // bh*S + q
    float* p = attn + row * S_;
    const int t    = threadIdx.x;
    const int wid  = t >> 5;
    const int lane = t & 31;

    float4 v0 = ((const float4*)p)[t];
    float4 v1 = ((const float4*)p)[t + 256];

    float m = fmaxf(fmaxf(fmaxf(v0.x, v0.y), fmaxf(v0.z, v0.w)),
                    fmaxf(fmaxf(v1.x, v1.y), fmaxf(v1.z, v1.w)));
#pragma unroll
    for (int o = 16; o > 0; o >>= 1)
        m = fmaxf(m, __shfl_xor_sync(0xffffffffu, m, o));
    if (lane == 0) smax[wid] = m;
    __syncthreads();
    float mr = smax[0];
#pragma unroll
    for (int i = 1; i < 8; i++) mr = fmaxf(mr, smax[i]);

    float e0x = __expf(v0.x - mr), e0y = __expf(v0.y - mr);
    float e0z = __expf(v0.z - mr), e0w = __expf(v0.w - mr);
    float e1x = __expf(v1.x - mr), e1y = __expf(v1.y - mr);
    float e1z = __expf(v1.z - mr), e1w = __expf(v1.w - mr);

    float s = ((e0x + e0y) + (e0z + e0w)) + ((e1x + e1y) + (e1z + e1w));
#pragma unroll
    for (int o = 16; o > 0; o >>= 1)
        s += __shfl_xor_sync(0xffffffffu, s, o);
    if (lane == 0) ssum[wid] = s;
    __syncthreads();
    float total = ssum[0];
#pragma unroll
    for (int i = 1; i < 8; i++) total += ssum[i];

    float inv = 1.0f / total;
    float4 r0 = make_float4(e0x * inv, e0y * inv, e0z * inv, e0w * inv);
    float4 r1 = make_float4(e1x * inv, e1y * inv, e1z * inv, e1w * inv);
    ((float4*)p)[t]       = r0;
    ((float4*)p)[t + 256] = r1;
}

// ---------------------------------------------------------------------------
// Kernel 3: output = P @ V. (R2, verified: 128x64 tile, 128 thr, 8x8 regs)
// ---------------------------------------------------------------------------
__global__ __launch_bounds__(128, 4)
void av_kernel(const float* __restrict__ attn, const float* __restrict__ v,
               float* __restrict__ out)
{
    __shared__ float sP[32][132];   // [k][q-row]
    __shared__ float sV[32][64];    // [k][d]

    const int bh = blockIdx.y;
    const int q0 = blockIdx.x * 128;
    const int t  = threadIdx.x;
    const int tq = t >> 3;          // 0..15 -> q rows tq*8..
    const int td = t & 7;           // 0..7  -> d cols td*8..

    const float* Pb = attn + ((size_t)bh * S_ + q0) * S_;
    const float* Vb = v + (size_t)bh * S_ * D_;

    float acc[8][8];
#pragma unroll
    for (int i = 0; i < 8; i++)
#pragma unroll
        for (int j = 0; j < 8; j++) acc[i][j] = 0.0f;

    for (int c0 = 0; c0 < S_; c0 += 32) {
        // Load P tile 128x32 transposed: 1024 float4 / 128 threads = 8 each.
#pragma unroll
        for (int i = 0; i < 8; i++) {
            int vid = t + i * 128;
            int row = vid >> 3;         // 0..127
            int c4  = (vid & 7) * 4;    // 0..28
            float4 a = *(const float4*)(Pb + (size_t)row * S_ + c0 + c4);
            sP[c4 + 0][row] = a.x; sP[c4 + 1][row] = a.y;
            sP[c4 + 2][row] = a.z; sP[c4 + 3][row] = a.w;
        }
        // Load V tile 32x64 natural layout: 512 float4 / 128 threads = 4 each.
#pragma unroll
        for (int i = 0; i < 4; i++) {
            int vid = t + i * 128;
            int row = vid >> 4;         // 0..31
            int c4  = (vid & 15) * 4;   // 0..60
            *(float4*)&sV[row][c4] =
                *(const float4*)(Vb + (size_t)(c0 + row) * D_ + c4);
        }
        __syncthreads();

#pragma unroll
        for (int kk = 0; kk < 32; kk++) {
            float4 a0 = *(const float4*)&sP[kk][tq * 8];
            float4 a1 = *(const float4*)&sP[kk][tq * 8 + 4];
            float4 b0 = *(const float4*)&sV[kk][td * 8];
            float4 b1 = *(const float4*)&sV[kk][td * 8 + 4];
            float av[8] = {a0.x, a0.y, a0.z, a0.w, a1.x, a1.y, a1.z, a1.w};
            float bv[8] = {b0.x, b0.y, b0.z, b0.w, b1.x, b1.y, b1.z, b1.w};
#pragma unroll
            for (int i = 0; i < 8; i++)
#pragma unroll
                for (int j = 0; j < 8; j++)
                    acc[i][j] = fmaf(av[i], bv[j], acc[i][j]);
        }
        __syncthreads();
    }

#pragma unroll
    for (int i = 0; i < 8; i++) {
        int qq = q0 + tq * 8 + i;
        float4* op = (float4*)(out + ((size_t)bh * S_ + qq) * D_ + td * 8);
        op[0] = make_float4(acc[i][0], acc[i][1], acc[i][2], acc[i][3]);
        op[1] = make_float4(acc[i][4], acc[i][5], acc[i][6], acc[i][7]);
    }
}

// ---------------------------------------------------------------------------
// Launch: out buffer = [output (B,H,S,D) | attention (B,H,S,S)]
// ---------------------------------------------------------------------------
extern "C" void kernel_launch(void* const* d_in, const int* in_sizes, int n_in,
                              void* d_out, int out_size)
{
    const float* q    = (const float*)d_in[0];
    const float* k    = (const float*)d_in[1];
    const float* v    = (const float*)d_in[2];
    const int*   mask = (const int*)d_in[3];

    float* out  = (float*)d_out;
    float* attn = out + (size_t)BH_ * S_ * D_;

    cudaFuncSetAttribute(qk_tf32_kernel,
                         cudaFuncAttributeMaxDynamicSharedMemorySize,
                         QK_SMEM_BYTES);

    dim3 g1(S_ / 128, S_ / 128, BH_);
    qk_tf32_kernel<<<g1, 256, QK_SMEM_BYTES>>>(q, k, mask, attn);

    softmax_kernel<<<(unsigned)(BH_ * S_), 256>>>(attn);

    dim3 g3(S_ / 128, BH_);
    av_kernel<<<g3, 128>>>(attn, v, out);
}

// round 12
// speedup vs baseline: 1.4365x; 1.0278x over previous
#include <cuda_runtime.h>
#include <cstdint>

#define B_  2
#define H_  12
#define S_  2048
#define D_  64
#define BH_ (B_ * H_)
#define SCALE_ 0.125f   // 1/sqrt(64)

#define QK_PAD 68       // stride ≡ 4 (mod 32) -> conflict-free fragment LDS
#define QK_SMEM_BYTES (2 * 128 * QK_PAD * 4)
#define AV_PAD 36       // stride ≡ 4 (mod 32), same property

// ---------------------------------------------------------------------------
// tf32 helpers
// ---------------------------------------------------------------------------
__device__ __forceinline__ uint32_t f2tf32(float x)
{
    uint32_t r;
    asm("cvt.rna.tf32.f32 %0, %1;" : "=r"(r) : "f"(x));
    return r;
}

__device__ __forceinline__ void split_tf32(float x, uint32_t& hi, uint32_t& lo)
{
    hi = f2tf32(x);
    lo = f2tf32(x - __uint_as_float(hi));
}

__device__ __forceinline__ void mma_tf32(float* c, const uint32_t* a, const uint32_t* b)
{
    asm("mma.sync.aligned.m16n8k8.row.col.f32.tf32.tf32.f32 "
        "{%0,%1,%2,%3}, {%4,%5,%6,%7}, {%8,%9}, {%0,%1,%2,%3};"
        : "+f"(c[0]), "+f"(c[1]), "+f"(c[2]), "+f"(c[3])
        : "r"(a[0]), "r"(a[1]), "r"(a[2]), "r"(a[3]), "r"(b[0]), "r"(b[1]));
}

// ---------------------------------------------------------------------------
// Kernel 1: QK^T via 3xTF32 tensor-core MMA + mask epilogue. (R11, verified)
// ---------------------------------------------------------------------------
__global__ __launch_bounds__(256)
void qk_tf32_kernel(const float* __restrict__ q, const float* __restrict__ k,
                    const int* __restrict__ mask, float* __restrict__ attn)
{
    extern __shared__ float smem[];
    float* sQ = smem;                 // [128][QK_PAD]
    float* sK = smem + 128 * QK_PAD;  // [128][QK_PAD]

    const int bh = blockIdx.z;
    const int b  = bh / H_;
    const int q0 = blockIdx.y * 128;
    const int k0 = blockIdx.x * 128;
    const int t    = threadIdx.x;
    const int lane = t & 31;
    const int wid  = t >> 5;
    const int wm   = wid >> 1;        // 0..3 -> q rows [wm*32, +32)
    const int wn   = wid & 1;         // 0..1 -> k cols [wn*64, +64)
    const int g    = lane >> 2;       // groupID 0..7
    const int tg   = lane & 3;        // thread-in-group 0..3

    const float* Qb = q + ((size_t)bh * S_ + q0) * D_;
    const float* Kb = k + ((size_t)bh * S_ + k0) * D_;

#pragma unroll
    for (int i = 0; i < 8; i++) {
        int vid = t + i * 256;
        int row = vid >> 4;           // 0..127
        int c4  = (vid & 15) * 4;     // 0..60
        *(float4*)&sQ[row * QK_PAD + c4] = *(const float4*)(Qb + (size_t)row * D_ + c4);
        *(float4*)&sK[row * QK_PAD + c4] = *(const float4*)(Kb + (size_t)row * D_ + c4);
    }
    __syncthreads();

    float acc[2][8][4];
#pragma unroll
    for (int mt = 0; mt < 2; mt++)
#pragma unroll
        for (int nt = 0; nt < 8; nt++)
#pragma unroll
            for (int r = 0; r < 4; r++) acc[mt][nt][r] = 0.0f;

#pragma unroll
    for (int ks = 0; ks < 8; ks++) {
        const int kb = ks * 8 + tg;

        uint32_t ahi[2][4], alo[2][4];
#pragma unroll
        for (int mt = 0; mt < 2; mt++) {
            int r = wm * 32 + mt * 16 + g;
            split_tf32(sQ[r * QK_PAD + kb],           ahi[mt][0], alo[mt][0]);
            split_tf32(sQ[(r + 8) * QK_PAD + kb],     ahi[mt][1], alo[mt][1]);
            split_tf32(sQ[r * QK_PAD + kb + 4],       ahi[mt][2], alo[mt][2]);
            split_tf32(sQ[(r + 8) * QK_PAD + kb + 4], ahi[mt][3], alo[mt][3]);
        }

        uint32_t bhi[8][2], blo[8][2];
#pragma unroll
        for (int nt = 0; nt < 8; nt++) {
            int cc = wn * 64 + nt * 8 + g;
            split_tf32(sK[cc * QK_PAD + kb],     bhi[nt][0], blo[nt][0]);
            split_tf32(sK[cc * QK_PAD + kb + 4], bhi[nt][1], blo[nt][1]);
        }

#pragma unroll
        for (int mt = 0; mt < 2; mt++)
#pragma unroll
            for (int nt = 0; nt < 8; nt++) {
                mma_tf32(acc[mt][nt], ahi[mt], bhi[nt]);
                mma_tf32(acc[mt][nt], ahi[mt], blo[nt]);
                mma_tf32(acc[mt][nt], alo[mt], bhi[nt]);
            }
    }

#pragma unroll
    for (int mt = 0; mt < 2; mt++)
#pragma unroll
        for (int nt = 0; nt < 8; nt++)
#pragma unroll
            for (int rr = 0; rr < 2; rr++) {
                int qq = q0 + wm * 32 + mt * 16 + g + 8 * rr;
                int kc = k0 + wn * 64 + nt * 8 + 2 * tg;
                int2 m2 = *(const int2*)(mask + ((size_t)b * S_ + qq) * S_ + kc);
                float2 r;
                r.x = (m2.x == 0) ? 1e-9f : acc[mt][nt][2 * rr + 0] * SCALE_;
                r.y = (m2.y == 0) ? 1e-9f : acc[mt][nt][2 * rr + 1] * SCALE_;
                *(float2*)(attn + ((size_t)bh * S_ + qq) * S_ + kc) = r;
            }
}

// ---------------------------------------------------------------------------
// Kernel 2: in-place row softmax over the attention region. (R2, verified)
// ---------------------------------------------------------------------------
__global__ __launch_bounds__(256)
void softmax_kernel(float* __restrict__ attn)
{
    __shared__ float smax[8];
    __shared__ float ssum[8];

    const size_t row = blockIdx.x;          // bh*S + q
    float* p = attn + row * S_;
    const int t    = threadIdx.x;
    const int wid  = t >> 5;
    const int lane = t & 31;

    float4 v0 = ((const float4*)p)[t];
    float4 v1 = ((const float4*)p)[t + 256];

    float m = fmaxf(fmaxf(fmaxf(v0.x, v0.y), fmaxf(v0.z, v0.w)),
                    fmaxf(fmaxf(v1.x, v1.y), fmaxf(v1.z, v1.w)));
#pragma unroll
    for (int o = 16; o > 0; o >>= 1)
        m = fmaxf(m, __shfl_xor_sync(0xffffffffu, m, o));
    if (lane == 0) smax[wid] = m;
    __syncthreads();
    float mr = smax[0];
#pragma unroll
    for (int i = 1; i < 8; i++) mr = fmaxf(mr, smax[i]);

    float e0x = __expf(v0.x - mr), e0y = __expf(v0.y - mr);
    float e0z = __expf(v0.z - mr), e0w = __expf(v0.w - mr);
    float e1x = __expf(v1.x - mr), e1y = __expf(v1.y - mr);
    float e1z = __expf(v1.z - mr), e1w = __expf(v1.w - mr);

    float s = ((e0x + e0y) + (e0z + e0w)) + ((e1x + e1y) + (e1z + e1w));
#pragma unroll
    for (int o = 16; o > 0; o >>= 1)
        s += __shfl_xor_sync(0xffffffffu, s, o);
    if (lane == 0) ssum[wid] = s;
    __syncthreads();
    float total = ssum[0];
#pragma unroll
    for (int i = 1; i < 8; i++) total += ssum[i];

    float inv = 1.0f / total;
    float4 r0 = make_float4(e0x * inv, e0y * inv, e0z * inv, e0w * inv);
    float4 r1 = make_float4(e1x * inv, e1y * inv, e1z * inv, e1w * inv);
    ((float4*)p)[t]       = r0;
    ((float4*)p)[t + 256] = r1;
}

// ---------------------------------------------------------------------------
// Kernel 3: output = P @ V via 3xTF32 tensor-core MMA.
// C-tile 128q x 64d, 256 threads (8 warps, 4m x 2n), warp tile 32x32.
// k-chunks of 32: sP[128][36] row-major, sVT[64][36] = V transposed.
// Same fragment/accumulator mapping as qk_tf32 (verified).
// ---------------------------------------------------------------------------
__global__ __launch_bounds__(256)
void av_tf32_kernel(const float* __restrict__ attn, const float* __restrict__ v,
                    float* __restrict__ out)
{
    __shared__ float sP[128][AV_PAD];
    __shared__ float sVT[64][AV_PAD];

    const int bh = blockIdx.y;
    const int q0 = blockIdx.x * 128;
    const int t    = threadIdx.x;
    const int lane = t & 31;
    const int wid  = t >> 5;
    const int wm   = wid >> 1;        // 0..3 -> q rows [wm*32, +32)
    const int wn   = wid & 1;         // 0..1 -> d cols [wn*32, +32)
    const int g    = lane >> 2;
    const int tg   = lane & 3;

    const float* Pb = attn + ((size_t)bh * S_ + q0) * S_;
    const float* Vb = v + (size_t)bh * S_ * D_;

    // V transpose-load mapping: lane = k-row (conflict-free STS), warp-constant d.
    const int vrow = t & 31;          // k-row within chunk
    const int vc4  = (t >> 5) * 4;    // d-offset 0..28 (with i*32: 0..60)

    float acc[2][4][4];
#pragma unroll
    for (int mt = 0; mt < 2; mt++)
#pragma unroll
        for (int nt = 0; nt < 4; nt++)
#pragma unroll
            for (int r = 0; r < 4; r++) acc[mt][nt][r] = 0.0f;

    for (int c0 = 0; c0 < S_; c0 += 32) {
        // P chunk 128x32: 1024 float4, 4/thread, coalesced, row-major into sP.
#pragma unroll
        for (int i = 0; i < 4; i++) {
            int vid = t + i * 256;
            int row = vid >> 3;           // 0..127
            int c4  = (vid & 7) * 4;      // 0..28
            *(float4*)&sP[row][c4] = *(const float4*)(Pb + (size_t)row * S_ + c0 + c4);
        }
        // V chunk 32x64 -> sVT[d][k]. Two d-halves per thread (vc4, vc4+32).
#pragma unroll
        for (int i = 0; i < 2; i++) {
            int dd = vc4 + i * 32;
            float4 b = *(const float4*)(Vb + (size_t)(c0 + vrow) * D_ + dd);
            sVT[dd + 0][vrow] = b.x; sVT[dd + 1][vrow] = b.y;
            sVT[dd + 2][vrow] = b.z; sVT[dd + 3][vrow] = b.w;
        }
        __syncthreads();

#pragma unroll
        for (int ks = 0; ks < 4; ks++) {
            const int kb = ks * 8 + tg;

            uint32_t ahi[2][4], alo[2][4];
#pragma unroll
            for (int mt = 0; mt < 2; mt++) {
                int r = wm * 32 + mt * 16 + g;
                split_tf32(sP[r][kb],          ahi[mt][0], alo[mt][0]);
                split_tf32(sP[r + 8][kb],      ahi[mt][1], alo[mt][1]);
                split_tf32(sP[r][kb + 4],      ahi[mt][2], alo[mt][2]);
                split_tf32(sP[r + 8][kb + 4],  ahi[mt][3], alo[mt][3]);
            }

            uint32_t bhi[4][2], blo[4][2];
#pragma unroll
            for (int nt = 0; nt < 4; nt++) {
                int cc = wn * 32 + nt * 8 + g;
                split_tf32(sVT[cc][kb],     bhi[nt][0], blo[nt][0]);
                split_tf32(sVT[cc][kb + 4], bhi[nt][1], blo[nt][1]);
            }

#pragma unroll
            for (int mt = 0; mt < 2; mt++)
#pragma unroll
                for (int nt = 0; nt < 4; nt++) {
                    mma_tf32(acc[mt][nt], ahi[mt], bhi[nt]);
                    mma_tf32(acc[mt][nt], ahi[mt], blo[nt]);
                    mma_tf32(acc[mt][nt], alo[mt], bhi[nt]);
                }
        }
        __syncthreads();
    }

    // Epilogue: same C fragment layout as qk.
#pragma unroll
    for (int mt = 0; mt < 2; mt++)
#pragma unroll
        for (int nt = 0; nt < 4; nt++)
#pragma unroll
            for (int rr = 0; rr < 2; rr++) {
                int qq = q0 + wm * 32 + mt * 16 + g + 8 * rr;
                int dc = wn * 32 + nt * 8 + 2 * tg;
                float2 r;
                r.x = acc[mt][nt][2 * rr + 0];
                r.y = acc[mt][nt][2 * rr + 1];
                *(float2*)(out + ((size_t)bh * S_ + qq) * D_ + dc) = r;
            }
}

// ---------------------------------------------------------------------------
// Launch: out buffer = [output (B,H,S,D) | attention (B,H,S,S)]
// ---------------------------------------------------------------------------
extern "C" void kernel_launch(void* const* d_in, const int* in_sizes, int n_in,
                              void* d_out, int out_size)
{
    const float* q    = (const float*)d_in[0];
    const float* k    = (const float*)d_in[1];
    const float* v    = (const float*)d_in[2];
    const int*   mask = (const int*)d_in[3];

    float* out  = (float*)d_out;
    float* attn = out + (size_t)BH_ * S_ * D_;

    cudaFuncSetAttribute(qk_tf32_kernel,
                         cudaFuncAttributeMaxDynamicSharedMemorySize,
                         QK_SMEM_BYTES);

    dim3 g1(S_ / 128, S_ / 128, BH_);
    qk_tf32_kernel<<<g1, 256, QK_SMEM_BYTES>>>(q, k, mask, attn);

    softmax_kernel<<<(unsigned)(BH_ * S_), 256>>>(attn);

    dim3 g3(S_ / 128, BH_);
    av_tf32_kernel<<<g3, 256>>>(attn, v, out);
}